// round 11
// baseline (speedup 1.0000x reference)
#include <cuda_runtime.h>
#include <cuda_bf16.h>
#include <math.h>
#include <stdint.h>

// ---------------- problem constants -----------------------------------------
#define TOK   1024
#define D     1024
#define HQ    2048
#define HEADS 8
#define QD    256
#define HALF  128
#define NK    32
#define DTK   4
#define NEXP  128
#define E     1024
#define O     1024
#define KDIM  1024

// ---------------- scratch (~35 MB of __device__ globals) ----------------------
__device__ __align__(256) float g_q[TOK * HQ];               // 8MB; low 4MB->eh, high 4MB->C planes
__device__ __align__(256) __nv_bfloat16 g_hid[3 * TOK * D];  // 6MB  (h,m,l)
__device__ __align__(256) __nv_bfloat16 g_wqT[3 * HQ * D];   // 12MB (transposed h,m,l)
__device__ __align__(256) __nv_bfloat16 g_dwn[2 * E * D];    // 4MB  (h,l)
__device__ __align__(256) __nv_bfloat16 g_upT[2 * O * E];    // 4MB  (transposed h,l)
__device__ float g_sums[QD];
__device__ float g_sqs[QD];
__device__ float g_k0n[NK * HALF];
__device__ float g_k1n[NK * HALF];
__device__ unsigned short g_idx[TOK * NEXP];
__device__ float g_w[TOK * NEXP];

// ---------------- helpers ----------------------------------------------------
__device__ __forceinline__ uint32_t s2u(const void* p) {
    uint32_t r;
    asm("{ .reg .u64 t; cvta.to.shared.u64 t, %1; cvt.u32.u64 %0, t; }"
        : "=r"(r) : "l"(p));
    return r;
}

// ---------------- plane-precomputed bf16 warp-MMA GEMM ------------------------
// C[m0:+128, n0:+128] = sum_passes A_pa @ B_pb^T.  A planes [P][M][K] bf16,
// B planes [P][N][K] bf16 (pre-transposed). fp32 out (+bias).
// BK=16, static smem (P3: 48KB, P2: 32KB), depth-2 cp.async double buffer,
// 512 thr / 16 warps (4M x 4N of 32x32 warp tiles).
template<int P, int NP>
__global__ __launch_bounds__(512, 1)
void gemm_planes(const __nv_bfloat16* __restrict__ A,
                 const __nv_bfloat16* __restrict__ B,
                 const float* __restrict__ bias,
                 float* __restrict__ Cout, int ldc, int aPl, int bPl)
{
    constexpr int BKB   = 32;                // bytes per row per plane (BK=16)
    constexpr int APL   = 128 * BKB;         // 4KB per plane
    constexpr int BPL   = 128 * BKB;         // 4KB per plane
    constexpr int STAGE = P * (APL + BPL);   // P3: 24KB, P2: 16KB
    constexpr int NCHA  = P * 128 * 2;       // 16B chunks for A per stage
    constexpr int NCH   = NCHA + P * 128 * 2;
    constexpr int NIT   = KDIM / 16;         // 64

    __shared__ __align__(1024) char smem[2 * STAGE];
    const uint32_t sbase = s2u(smem);
    const int tid = threadIdx.x, w = tid >> 5, l = tid & 31;
    const int m0 = blockIdx.y * 128, n0 = blockIdx.x * 128;
    const int wm = (w & 3) * 32, wn = (w >> 2) * 32;

    float acc[2][4][4];
    #pragma unroll
    for (int a = 0; a < 2; a++)
        #pragma unroll
        for (int b = 0; b < 4; b++)
            #pragma unroll
            for (int c = 0; c < 4; c++) acc[a][b][c] = 0.f;

    auto swz = [](int c, int r) -> int { return c ^ ((r >> 2) & 1); };

    auto issue = [&](int it) {
        const int s = it & 1;
        const int k0 = it * 16;
        const uint32_t sb0 = sbase + (uint32_t)s * STAGE;
        #pragma unroll
        for (int q = 0; q < (NCH + 511) / 512; q++) {
            const int id = tid + q * 512;
            if (id < NCH) {
                uint32_t dst; const __nv_bfloat16* src;
                if (id < NCHA) {
                    const int p = id >> 8;            // id / 256
                    const int rem = id & 255;
                    const int r = rem >> 1, c = rem & 1;
                    dst = sb0 + (uint32_t)(p * APL + r * BKB + swz(c, r) * 16);
                    src = A + (size_t)p * aPl + (size_t)(m0 + r) * KDIM + k0 + c * 8;
                } else {
                    const int id2 = id - NCHA;
                    const int p = id2 >> 8;
                    const int rem = id2 & 255;
                    const int r = rem >> 1, c = rem & 1;
                    dst = sb0 + (uint32_t)(P * APL + p * BPL + r * BKB + swz(c, r) * 16);
                    src = B + (size_t)p * bPl + (size_t)(n0 + r) * KDIM + k0 + c * 8;
                }
                asm volatile("cp.async.cg.shared.global [%0], [%1], 16;\n"
                             :: "r"(dst), "l"(src));
            }
        }
        asm volatile("cp.async.commit_group;\n" ::: "memory");
    };

    const int rg = ((l >> 3) & 1) * 8 + (l & 7);
    const int ch = l >> 4;

    issue(0);
    issue(1);
    for (int i = 0; i < NIT; i++) {
        asm volatile("cp.async.wait_group 1;\n" ::: "memory");
        __syncthreads();
        const uint32_t sb0 = sbase + (uint32_t)(i & 1) * STAGE;

        #pragma unroll
        for (int ps = 0; ps < NP; ps++) {
            const int PA6[6] = {0,0,1,0,1,2}, PB6[6] = {0,1,0,2,1,0};
            const int PA3[3] = {0,0,1},       PB3[3] = {0,1,0};
            const int pa = (NP == 6) ? PA6[ps] : PA3[ps];
            const int pb = (NP == 6) ? PB6[ps] : PB3[ps];
            uint32_t af[2][4];
            #pragma unroll
            for (int mt = 0; mt < 2; mt++) {
                const int row = wm + mt * 16 + rg;
                const uint32_t ad = sb0 + (uint32_t)(pa * APL + row * BKB + swz(ch, row) * 16);
                asm volatile("ldmatrix.sync.aligned.m8n8.x4.shared.b16 {%0,%1,%2,%3}, [%4];\n"
                    : "=r"(af[mt][0]), "=r"(af[mt][1]), "=r"(af[mt][2]), "=r"(af[mt][3])
                    : "r"(ad));
            }
            uint32_t bfr[4][2];
            #pragma unroll
            for (int np = 0; np < 2; np++) {
                const int row = wn + np * 16 + rg;
                const uint32_t ad = sb0 + (uint32_t)(P * APL + pb * BPL + row * BKB + swz(ch, row) * 16);
                uint32_t b0, b1, b2, b3;
                asm volatile("ldmatrix.sync.aligned.m8n8.x4.shared.b16 {%0,%1,%2,%3}, [%4];\n"
                    : "=r"(b0), "=r"(b1), "=r"(b2), "=r"(b3) : "r"(ad));
                bfr[np * 2 + 0][0] = b0; bfr[np * 2 + 0][1] = b2;
                bfr[np * 2 + 1][0] = b1; bfr[np * 2 + 1][1] = b3;
            }
            #pragma unroll
            for (int mt = 0; mt < 2; mt++)
                #pragma unroll
                for (int nt = 0; nt < 4; nt++)
                    asm volatile(
                        "mma.sync.aligned.m16n8k16.row.col.f32.bf16.bf16.f32 "
                        "{%0,%1,%2,%3}, {%4,%5,%6,%7}, {%8,%9}, {%0,%1,%2,%3};\n"
                        : "+f"(acc[mt][nt][0]), "+f"(acc[mt][nt][1]),
                          "+f"(acc[mt][nt][2]), "+f"(acc[mt][nt][3])
                        : "r"(af[mt][0]), "r"(af[mt][1]), "r"(af[mt][2]), "r"(af[mt][3]),
                          "r"(bfr[nt][0]), "r"(bfr[nt][1]));
        }
        __syncthreads();
        if (i + 2 < NIT) issue(i + 2);
        else asm volatile("cp.async.commit_group;\n" ::: "memory");
    }

    #pragma unroll
    for (int mt = 0; mt < 2; mt++) {
        const int row = m0 + wm + mt * 16 + (l >> 2);
        #pragma unroll
        for (int nt = 0; nt < 4; nt++) {
            const int col = n0 + wn + nt * 8 + (l & 3) * 2;
            float b0 = 0.f, b1 = 0.f;
            if (bias) { b0 = bias[col]; b1 = bias[col + 1]; }
            *(float2*)(Cout + (size_t)row * ldc + col) =
                make_float2(acc[mt][nt][0] + b0, acc[mt][nt][1] + b1);
            *(float2*)(Cout + (size_t)(row + 8) * ldc + col) =
                make_float2(acc[mt][nt][2] + b0, acc[mt][nt][3] + b1);
        }
    }
}

// ---------------- one fused conversion kernel ---------------------------------
// grid layout: [0,4096) hidden conv3 | [4096,8192) down conv2
//              [8192,10240) Wq convT3 | [10240,11264) up convT2
__global__ __launch_bounds__(256)
void conv_all(const float* __restrict__ hidden, const float* __restrict__ Wq,
              const float* __restrict__ down, const float* __restrict__ up,
              __nv_bfloat16* __restrict__ hid, __nv_bfloat16* __restrict__ wqT,
              __nv_bfloat16* __restrict__ dwn, __nv_bfloat16* __restrict__ upT)
{
    const int b = blockIdx.x;
    const int tid = threadIdx.x;
    if (b < 8192) {
        const bool isH = (b < 4096);
        const int i = (isH ? b : b - 4096) * 256 + tid;
        const float v = isH ? hidden[i] : down[i];
        const __nv_bfloat16 h = __float2bfloat16(v);
        const float r1 = v - __bfloat162float(h);
        const __nv_bfloat16 m = __float2bfloat16(r1);
        if (isH) {
            hid[i] = h;
            hid[TOK * D + i] = m;
            hid[2 * TOK * D + i] = __float2bfloat16(r1 - __bfloat162float(m));
        } else {
            dwn[i] = h;
            dwn[E * D + i] = m;
        }
    } else {
        __shared__ float t[32][33];
        const bool isW = (b < 10240);
        const int idx = isW ? (b - 8192) : (b - 10240);
        const int N = isW ? HQ : O;
        const int nb = N / 32;
        const int nx = (idx % nb) * 32, ky = (idx / nb) * 32;
        const int tx = tid & 31, ty = tid >> 5;   // 32 x 8
        const float* in = isW ? Wq : up;
        #pragma unroll
        for (int j = 0; j < 32; j += 8)
            t[ty + j][tx] = in[(size_t)(ky + ty + j) * N + nx + tx];
        __syncthreads();
        #pragma unroll
        for (int j = 0; j < 32; j += 8) {
            const int n = nx + ty + j;
            const int k = ky + tx;
            const float v = t[tx][ty + j];
            const __nv_bfloat16 h = __float2bfloat16(v);
            const float r1 = v - __bfloat162float(h);
            const __nv_bfloat16 m = __float2bfloat16(r1);
            if (isW) {
                wqT[(size_t)n * KDIM + k] = h;
                wqT[HQ * D + (size_t)n * KDIM + k] = m;
                wqT[2 * HQ * D + (size_t)n * KDIM + k] =
                    __float2bfloat16(r1 - __bfloat162float(m));
            } else {
                upT[(size_t)n * KDIM + k] = h;
                upT[O * E + (size_t)n * KDIM + k] = m;
            }
        }
    }
}

// ---------------- norm keys + zero stats (one launch) --------------------------
__global__ __launch_bounds__(128)
void norm_keys_zero_kernel(const float* __restrict__ k0,
                           const float* __restrict__ k1) {
    const int row = blockIdx.x;
    const int tid = threadIdx.x;
    if (row == 2 * NK) {            // extra block: zero BN stat accumulators
        g_sums[tid] = 0.f; g_sums[tid + 128] = 0.f;
        g_sqs[tid] = 0.f;  g_sqs[tid + 128] = 0.f;
        return;
    }
    const float* src = (row < NK) ? (k0 + (size_t)row * HALF)
                                  : (k1 + (size_t)(row - NK) * HALF);
    float* dst = (row < NK) ? (g_k0n + (size_t)row * HALF)
                            : (g_k1n + (size_t)(row - NK) * HALF);
    __shared__ float red[128];
    float v = src[tid];
    red[tid] = v * v;
    __syncthreads();
    for (int s = 64; s > 0; s >>= 1) {
        if (tid < s) red[tid] += red[tid + s];
        __syncthreads();
    }
    float n = sqrtf(red[0]);
    dst[tid] = v / fmaxf(n, 1e-12f);
}

// ---------------- BN partial sums: 128 blocks x 8 rows -------------------------
__global__ __launch_bounds__(256)
void stats_partial_kernel() {
    const int tid = threadIdx.x;        // feature 0..255
    const int rowStart = blockIdx.x * 8;
    float s = 0.f, sq = 0.f;
    #pragma unroll
    for (int r = 0; r < 8; r++) {
        const float* row = g_q + (size_t)(rowStart + r) * HQ;
        #pragma unroll
        for (int h = 0; h < HEADS; h++) {
            float v = row[h * QD + tid];
            s += v; sq += v * v;
        }
    }
    atomicAdd(&g_sums[tid], s);
    atomicAdd(&g_sqs[tid], sq);
}

// ---------------- score: BN(from raw sums) + L2norm + dots + top4x4 + softmax --
__global__ __launch_bounds__(128)
void score_kernel(const float* __restrict__ gamma,
                  const float* __restrict__ beta) {
    const int u = blockIdx.x;
    const int t = u >> 3;
    const int h = u & 7;
    const int tid = threadIdx.x;

    __shared__ float q0[HALF], q1[HALF];
    __shared__ float red0[128], red1[128];
    __shared__ float s0s[NK], s1s[NK];
    __shared__ float ts0[DTK], ts1[DTK];
    __shared__ int   ti0[DTK], ti1[DTK];
    __shared__ float combS[16];
    __shared__ int   combI[16];
    __shared__ float smx, ssum;

    const float invN = 1.0f / (float)(TOK * HEADS);
    const float* qrow = g_q + (size_t)t * HQ + h * QD;
    float a = qrow[tid];
    float b = qrow[HALF + tid];
    {
        const float m0v = g_sums[tid] * invN;
        const float v0 = g_sqs[tid] * invN - m0v * m0v;
        const float m1v = g_sums[HALF + tid] * invN;
        const float v1 = g_sqs[HALF + tid] * invN - m1v * m1v;
        a = (a - m0v) * rsqrtf(v0 + 1e-5f) * gamma[tid] + beta[tid];
        b = (b - m1v) * rsqrtf(v1 + 1e-5f) * gamma[HALF + tid] + beta[HALF + tid];
    }

    red0[tid] = a * a;
    red1[tid] = b * b;
    __syncthreads();
    for (int s = 64; s > 0; s >>= 1) {
        if (tid < s) { red0[tid] += red0[tid + s]; red1[tid] += red1[tid + s]; }
        __syncthreads();
    }
    float n0 = fmaxf(sqrtf(red0[0]), 1e-12f);
    float n1 = fmaxf(sqrtf(red1[0]), 1e-12f);
    q0[tid] = a / n0;
    q1[tid] = b / n1;
    __syncthreads();

    const int w = tid >> 5, l = tid & 31;
    for (int j = w; j < NK; j += 4) {
        const float* kr0 = g_k0n + j * HALF;
        const float* kr1 = g_k1n + j * HALF;
        float d0 = kr0[l] * q0[l] + kr0[l + 32] * q0[l + 32]
                 + kr0[l + 64] * q0[l + 64] + kr0[l + 96] * q0[l + 96];
        float d1 = kr1[l] * q1[l] + kr1[l + 32] * q1[l + 32]
                 + kr1[l + 64] * q1[l + 64] + kr1[l + 96] * q1[l + 96];
        #pragma unroll
        for (int off = 16; off; off >>= 1) {
            d0 += __shfl_down_sync(0xffffffffu, d0, off);
            d1 += __shfl_down_sync(0xffffffffu, d1, off);
        }
        if (l == 0) { s0s[j] = d0; s1s[j] = d1; }
    }
    __syncthreads();

    // warp-parallel top-4 per axis (ties -> lowest index, matching lax.top_k)
    if (w < 2) {
        float v = (w == 0) ? s0s[l] : s1s[l];
        #pragma unroll
        for (int p = 0; p < DTK; p++) {
            float bv = v; int bi = l;
            #pragma unroll
            for (int off = 16; off; off >>= 1) {
                float ov = __shfl_down_sync(0xffffffffu, bv, off);
                int oi = __shfl_down_sync(0xffffffffu, bi, off);
                if (ov > bv || (ov == bv && oi < bi)) { bv = ov; bi = oi; }
            }
            bv = __shfl_sync(0xffffffffu, bv, 0);
            bi = __shfl_sync(0xffffffffu, bi, 0);
            if (l == 0) {
                if (w == 0) { ts0[p] = bv; ti0[p] = bi; }
                else        { ts1[p] = bv; ti1[p] = bi; }
            }
            if (l == bi) v = -1e30f;
        }
    }
    __syncthreads();

    if (tid < 16) {
        int i = tid >> 2, j = tid & 3;
        combS[tid] = ts0[i] + ts1[j];
        combI[tid] = ti0[i] * NK + ti1[j];
    }
    __syncthreads();
    if (tid == 0) {
        float m = -1e30f;
        for (int k = 0; k < 16; k++) m = fmaxf(m, combS[k]);
        float s = 0.f;
        for (int k = 0; k < 16; k++) s += expf(combS[k] - m);
        smx = m; ssum = s;
    }
    __syncthreads();
    if (tid < 16) {
        g_idx[(size_t)u * 16 + tid] = (unsigned short)combI[tid];
        g_w[(size_t)u * 16 + tid]   = expf(combS[tid] - smx) / ssum;
    }
}

// ---------------- eh -> C bf16 planes (gelu * softmax weight, scattered) ------
__global__ __launch_bounds__(256)
void transformC_kernel(const float* __restrict__ eh,
                       __nv_bfloat16* __restrict__ c0,
                       __nv_bfloat16* __restrict__ c1) {
    __shared__ float acc[E];
    const int t = blockIdx.x;
    const int tid = threadIdx.x;
    for (int i = tid; i < E; i += 256) acc[i] = 0.f;
    __syncthreads();
    if (tid < NEXP) {
        const int idx = (int)g_idx[(size_t)t * NEXP + tid];
        const float v = eh[(size_t)t * E + idx];
        const float g = 0.5f * v * (1.0f + erff(v * 0.70710678118654752f));
        atomicAdd(&acc[idx], g * g_w[(size_t)t * NEXP + tid]);
    }
    __syncthreads();
    for (int i = tid; i < E; i += 256) {
        const float v = acc[i];
        const __nv_bfloat16 h = __float2bfloat16(v);
        c0[(size_t)t * E + i] = h;
        c1[(size_t)t * E + i] = __float2bfloat16(v - __bfloat162float(h));
    }
}

// ---------------- launch -------------------------------------------------------
extern "C" void kernel_launch(void* const* d_in, const int* in_sizes, int n_in,
                              void* d_out, int out_size) {
    const float* hidden = (const float*)d_in[0];   // [2,512,1024]
    const float* Wq     = (const float*)d_in[1];   // [1024,2048]
    const float* bq     = (const float*)d_in[2];   // [2048]
    const float* gamma  = (const float*)d_in[3];   // [256]
    const float* beta   = (const float*)d_in[4];   // [256]
    const float* k0     = (const float*)d_in[5];   // [32,128]
    const float* k1     = (const float*)d_in[6];   // [32,128]
    const float* down   = (const float*)d_in[7];   // [1024,1024]
    const float* up     = (const float*)d_in[8];   // [1024,1024]
    float* out = (float*)d_out;                    // [2,512,1024]

    float* qbuf = nullptr;
    __nv_bfloat16 *hid = nullptr, *wqT = nullptr, *dwn = nullptr, *upT = nullptr;
    cudaGetSymbolAddress((void**)&qbuf, g_q);
    cudaGetSymbolAddress((void**)&hid, g_hid);
    cudaGetSymbolAddress((void**)&wqT, g_wqT);
    cudaGetSymbolAddress((void**)&dwn, g_dwn);
    cudaGetSymbolAddress((void**)&upT, g_upT);
    float* ehBuf = qbuf;                                   // low 4MB of g_q
    __nv_bfloat16* cp0 = (__nv_bfloat16*)(qbuf + TOK * E); // high 4MB of g_q
    __nv_bfloat16* cp1 = cp0 + TOK * E;

    // all plane conversions in one kernel; key norm + stat zeroing in one
    conv_all<<<11264, 256>>>(hidden, Wq, down, up, hid, wqT, dwn, upT);
    norm_keys_zero_kernel<<<2 * NK + 1, 128>>>(k0, k1);

    // q = hidden @ Wq + bq (6-pass h/m/l: fp32-grade routing)
    gemm_planes<3, 6><<<dim3(HQ / 128, TOK / 128), 512>>>(
        hid, wqT, bq, qbuf, HQ, TOK * D, HQ * D);

    // BN partial sums (mean/var finalized inside score_kernel)
    stats_partial_kernel<<<128, 256>>>();
    score_kernel<<<TOK * HEADS, 128>>>(gamma, beta);

    // eh_all = hidden @ down^T (3-pass h/l); overwrites dead q (low half)
    gemm_planes<2, 3><<<dim3(E / 128, TOK / 128), 512>>>(
        hid, dwn, nullptr, ehBuf, E, TOK * D, E * D);

    // eh -> C planes (gelu * softmax weight, scattered)
    transformC_kernel<<<TOK, 256>>>(ehBuf, cp0, cp1);

    // out = C @ up (3-pass h/l)
    gemm_planes<2, 3><<<dim3(O / 128, TOK / 128), 512>>>(
        cp0, upT, nullptr, out, O, TOK * E, O * E);
}

// round 13
// speedup vs baseline: 1.2244x; 1.2244x over previous
#include <cuda_runtime.h>
#include <cuda_bf16.h>
#include <math.h>
#include <stdint.h>

// ---------------- problem constants -----------------------------------------
#define TOK   1024
#define D     1024
#define HQ    2048
#define HEADS 8
#define QD    256
#define HALF  128
#define NK    32
#define DTK   4
#define NEXP  128
#define E     1024
#define O     1024
#define KDIM  1024

// ---------------- scratch (~35 MB of __device__ globals) ----------------------
__device__ __align__(256) float g_q[TOK * HQ];               // 8MB; low 4MB->eh, high 4MB->C planes
__device__ __align__(256) __nv_bfloat16 g_hid[3 * TOK * D];  // 6MB  (h,m,l)
__device__ __align__(256) __nv_bfloat16 g_wqT[3 * HQ * D];   // 12MB (transposed h,m,l)
__device__ __align__(256) __nv_bfloat16 g_dwn[2 * E * D];    // 4MB  (h,l)
__device__ __align__(256) __nv_bfloat16 g_upT[2 * O * E];    // 4MB  (transposed h,l)
__device__ float g_sums[QD];
__device__ float g_sqs[QD];
__device__ float g_k0n[NK * HALF];
__device__ float g_k1n[NK * HALF];
__device__ unsigned short g_idx[TOK * NEXP];
__device__ float g_w[TOK * NEXP];

// ---------------- helpers ----------------------------------------------------
__device__ __forceinline__ uint32_t s2u(const void* p) {
    uint32_t r;
    asm("{ .reg .u64 t; cvta.to.shared.u64 t, %1; cvt.u32.u64 %0, t; }"
        : "=r"(r) : "l"(p));
    return r;
}

// ---------------- plane-precomputed bf16 warp-MMA GEMM (round-9 proven) -------
// C[m0:+128, n0:+64] = sum_passes A_pa @ B_pb^T.  A planes [P][M][K] bf16,
// B planes [P][N][K] bf16 (pre-transposed). fp32 out (+bias).
// Static smem, depth-2 cp.async double buffer, 8 warps (4Mx2N of 32x32 tiles),
// 2 CTAs/SM for sync-bubble cover (128x128@1CTA/SM measured +60us regression).
template<int P, int NP, int BK>
__global__ __launch_bounds__(256, 2)
void gemm_planes(const __nv_bfloat16* __restrict__ A,
                 const __nv_bfloat16* __restrict__ B,
                 const float* __restrict__ bias,
                 float* __restrict__ Cout, int ldc, int aPl, int bPl)
{
    constexpr int CPR   = BK / 8;            // 16B chunks per row per plane
    constexpr int BKB   = BK * 2;            // bytes per row per plane
    constexpr int APL   = 128 * BKB;
    constexpr int BPL   = 64 * BKB;
    constexpr int STAGE = P * (APL + BPL);   // P3/BK16: 18KB; P2/BK32: 24KB
    constexpr int NCHA  = P * 128 * CPR;
    constexpr int NCH   = NCHA + P * 64 * CPR;
    constexpr int NIT   = KDIM / BK;
    constexpr int KT    = BK / 16;

    __shared__ __align__(1024) char smem[2 * STAGE];
    const uint32_t sbase = s2u(smem);
    const int tid = threadIdx.x, w = tid >> 5, l = tid & 31;
    const int m0 = blockIdx.y * 128, n0 = blockIdx.x * 64;
    const int wm = (w >> 1) * 32, wn = (w & 1) * 32;

    float acc[2][4][4];
    #pragma unroll
    for (int a = 0; a < 2; a++)
        #pragma unroll
        for (int b = 0; b < 4; b++)
            #pragma unroll
            for (int c = 0; c < 4; c++) acc[a][b][c] = 0.f;

    auto swz = [](int c, int r) -> int {
        return (BK == 16) ? (c ^ ((r >> 2) & 1)) : (c ^ ((r >> 1) & 3));
    };

    auto issue = [&](int it) {
        const int s = it & 1;
        const int k0 = it * BK;
        const uint32_t sb0 = sbase + (uint32_t)s * STAGE;
        #pragma unroll 2
        for (int id = tid; id < NCH; id += 256) {
            uint32_t dst; const __nv_bfloat16* src;
            if (id < NCHA) {
                const int p = id / (128 * CPR);
                const int rem = id - p * 128 * CPR;
                const int r = rem / CPR, c = rem - r * CPR;
                dst = sb0 + (uint32_t)(p * APL + r * BKB + swz(c, r) * 16);
                src = A + (size_t)p * aPl + (size_t)(m0 + r) * KDIM + k0 + c * 8;
            } else {
                const int id2 = id - NCHA;
                const int p = id2 / (64 * CPR);
                const int rem = id2 - p * 64 * CPR;
                const int r = rem / CPR, c = rem - r * CPR;
                dst = sb0 + (uint32_t)(P * APL + p * BPL + r * BKB + swz(c, r) * 16);
                src = B + (size_t)p * bPl + (size_t)(n0 + r) * KDIM + k0 + c * 8;
            }
            asm volatile("cp.async.cg.shared.global [%0], [%1], 16;\n"
                         :: "r"(dst), "l"(src));
        }
        asm volatile("cp.async.commit_group;\n" ::: "memory");
    };

    const int rg = ((l >> 3) & 1) * 8 + (l & 7);
    const int ch = l >> 4;

    issue(0);
    issue(1);
    for (int i = 0; i < NIT; i++) {
        asm volatile("cp.async.wait_group 1;\n" ::: "memory");
        __syncthreads();
        const uint32_t sb0 = sbase + (uint32_t)(i & 1) * STAGE;

        #pragma unroll
        for (int ps = 0; ps < NP; ps++) {
            const int PA6[6] = {0,0,1,0,1,2}, PB6[6] = {0,1,0,2,1,0};
            const int PA3[3] = {0,0,1},       PB3[3] = {0,1,0};
            const int pa = (NP == 6) ? PA6[ps] : PA3[ps];
            const int pb = (NP == 6) ? PB6[ps] : PB3[ps];
            #pragma unroll
            for (int kt = 0; kt < KT; kt++) {
                uint32_t af[2][4];
                #pragma unroll
                for (int mt = 0; mt < 2; mt++) {
                    const int row = wm + mt * 16 + rg;
                    const int c = kt * 2 + ch;
                    const uint32_t ad = sb0 + (uint32_t)(pa * APL + row * BKB + swz(c, row) * 16);
                    asm volatile("ldmatrix.sync.aligned.m8n8.x4.shared.b16 {%0,%1,%2,%3}, [%4];\n"
                        : "=r"(af[mt][0]), "=r"(af[mt][1]), "=r"(af[mt][2]), "=r"(af[mt][3])
                        : "r"(ad));
                }
                uint32_t bfr[4][2];
                #pragma unroll
                for (int np = 0; np < 2; np++) {
                    const int row = wn + np * 16 + rg;
                    const int c = kt * 2 + ch;
                    const uint32_t ad = sb0 + (uint32_t)(P * APL + pb * BPL + row * BKB + swz(c, row) * 16);
                    uint32_t b0, b1, b2, b3;
                    asm volatile("ldmatrix.sync.aligned.m8n8.x4.shared.b16 {%0,%1,%2,%3}, [%4];\n"
                        : "=r"(b0), "=r"(b1), "=r"(b2), "=r"(b3) : "r"(ad));
                    bfr[np * 2 + 0][0] = b0; bfr[np * 2 + 0][1] = b2;
                    bfr[np * 2 + 1][0] = b1; bfr[np * 2 + 1][1] = b3;
                }
                #pragma unroll
                for (int mt = 0; mt < 2; mt++)
                    #pragma unroll
                    for (int nt = 0; nt < 4; nt++)
                        asm volatile(
                            "mma.sync.aligned.m16n8k16.row.col.f32.bf16.bf16.f32 "
                            "{%0,%1,%2,%3}, {%4,%5,%6,%7}, {%8,%9}, {%0,%1,%2,%3};\n"
                            : "+f"(acc[mt][nt][0]), "+f"(acc[mt][nt][1]),
                              "+f"(acc[mt][nt][2]), "+f"(acc[mt][nt][3])
                            : "r"(af[mt][0]), "r"(af[mt][1]), "r"(af[mt][2]), "r"(af[mt][3]),
                              "r"(bfr[nt][0]), "r"(bfr[nt][1]));
            }
        }
        __syncthreads();
        if (i + 2 < NIT) issue(i + 2);
        else asm volatile("cp.async.commit_group;\n" ::: "memory");
    }

    #pragma unroll
    for (int mt = 0; mt < 2; mt++) {
        const int row = m0 + wm + mt * 16 + (l >> 2);
        #pragma unroll
        for (int nt = 0; nt < 4; nt++) {
            const int col = n0 + wn + nt * 8 + (l & 3) * 2;
            float b0 = 0.f, b1 = 0.f;
            if (bias) { b0 = bias[col]; b1 = bias[col + 1]; }
            *(float2*)(Cout + (size_t)row * ldc + col) =
                make_float2(acc[mt][nt][0] + b0, acc[mt][nt][1] + b1);
            *(float2*)(Cout + (size_t)(row + 8) * ldc + col) =
                make_float2(acc[mt][nt][2] + b0, acc[mt][nt][3] + b1);
        }
    }
}

// ---------------- one fused conversion kernel ---------------------------------
// grid layout: [0,4096) hidden conv3 | [4096,8192) down conv2
//              [8192,10240) Wq convT3 | [10240,11264) up convT2
__global__ __launch_bounds__(256)
void conv_all(const float* __restrict__ hidden, const float* __restrict__ Wq,
              const float* __restrict__ down, const float* __restrict__ up,
              __nv_bfloat16* __restrict__ hid, __nv_bfloat16* __restrict__ wqT,
              __nv_bfloat16* __restrict__ dwn, __nv_bfloat16* __restrict__ upT)
{
    const int b = blockIdx.x;
    const int tid = threadIdx.x;
    if (b < 8192) {
        const bool isH = (b < 4096);
        const int i = (isH ? b : b - 4096) * 256 + tid;
        const float v = isH ? hidden[i] : down[i];
        const __nv_bfloat16 h = __float2bfloat16(v);
        const float r1 = v - __bfloat162float(h);
        const __nv_bfloat16 m = __float2bfloat16(r1);
        if (isH) {
            hid[i] = h;
            hid[TOK * D + i] = m;
            hid[2 * TOK * D + i] = __float2bfloat16(r1 - __bfloat162float(m));
        } else {
            dwn[i] = h;
            dwn[E * D + i] = m;
        }
    } else {
        __shared__ float t[32][33];
        const bool isW = (b < 10240);
        const int idx = isW ? (b - 8192) : (b - 10240);
        const int N = isW ? HQ : O;
        const int nb = N / 32;
        const int nx = (idx % nb) * 32, ky = (idx / nb) * 32;
        const int tx = tid & 31, ty = tid >> 5;   // 32 x 8
        const float* in = isW ? Wq : up;
        #pragma unroll
        for (int j = 0; j < 32; j += 8)
            t[ty + j][tx] = in[(size_t)(ky + ty + j) * N + nx + tx];
        __syncthreads();
        #pragma unroll
        for (int j = 0; j < 32; j += 8) {
            const int n = nx + ty + j;
            const int k = ky + tx;
            const float v = t[tx][ty + j];
            const __nv_bfloat16 h = __float2bfloat16(v);
            const float r1 = v - __bfloat162float(h);
            const __nv_bfloat16 m = __float2bfloat16(r1);
            if (isW) {
                wqT[(size_t)n * KDIM + k] = h;
                wqT[HQ * D + (size_t)n * KDIM + k] = m;
                wqT[2 * HQ * D + (size_t)n * KDIM + k] =
                    __float2bfloat16(r1 - __bfloat162float(m));
            } else {
                upT[(size_t)n * KDIM + k] = h;
                upT[O * E + (size_t)n * KDIM + k] = m;
            }
        }
    }
}

// ---------------- norm keys + zero stats (one launch) --------------------------
__global__ __launch_bounds__(128)
void norm_keys_zero_kernel(const float* __restrict__ k0,
                           const float* __restrict__ k1) {
    const int row = blockIdx.x;
    const int tid = threadIdx.x;
    if (row == 2 * NK) {            // extra block: zero BN stat accumulators
        g_sums[tid] = 0.f; g_sums[tid + 128] = 0.f;
        g_sqs[tid] = 0.f;  g_sqs[tid + 128] = 0.f;
        return;
    }
    const float* src = (row < NK) ? (k0 + (size_t)row * HALF)
                                  : (k1 + (size_t)(row - NK) * HALF);
    float* dst = (row < NK) ? (g_k0n + (size_t)row * HALF)
                            : (g_k1n + (size_t)(row - NK) * HALF);
    __shared__ float red[128];
    float v = src[tid];
    red[tid] = v * v;
    __syncthreads();
    for (int s = 64; s > 0; s >>= 1) {
        if (tid < s) red[tid] += red[tid + s];
        __syncthreads();
    }
    float n = sqrtf(red[0]);
    dst[tid] = v / fmaxf(n, 1e-12f);
}

// ---------------- BN partial sums: 128 blocks x 8 rows -------------------------
__global__ __launch_bounds__(256)
void stats_partial_kernel() {
    const int tid = threadIdx.x;        // feature 0..255
    const int rowStart = blockIdx.x * 8;
    float s = 0.f, sq = 0.f;
    #pragma unroll
    for (int r = 0; r < 8; r++) {
        const float* row = g_q + (size_t)(rowStart + r) * HQ;
        #pragma unroll
        for (int h = 0; h < HEADS; h++) {
            float v = row[h * QD + tid];
            s += v; sq += v * v;
        }
    }
    atomicAdd(&g_sums[tid], s);
    atomicAdd(&g_sqs[tid], sq);
}

// ---------------- score: BN(from raw sums) + L2norm + dots + top4x4 + softmax --
__global__ __launch_bounds__(128)
void score_kernel(const float* __restrict__ gamma,
                  const float* __restrict__ beta) {
    const int u = blockIdx.x;
    const int t = u >> 3;
    const int h = u & 7;
    const int tid = threadIdx.x;

    __shared__ float q0[HALF], q1[HALF];
    __shared__ float red0[128], red1[128];
    __shared__ float s0s[NK], s1s[NK];
    __shared__ float ts0[DTK], ts1[DTK];
    __shared__ int   ti0[DTK], ti1[DTK];
    __shared__ float combS[16];
    __shared__ int   combI[16];
    __shared__ float smx, ssum;

    const float invN = 1.0f / (float)(TOK * HEADS);
    const float* qrow = g_q + (size_t)t * HQ + h * QD;
    float a = qrow[tid];
    float b = qrow[HALF + tid];
    {
        const float m0v = g_sums[tid] * invN;
        const float v0 = g_sqs[tid] * invN - m0v * m0v;
        const float m1v = g_sums[HALF + tid] * invN;
        const float v1 = g_sqs[HALF + tid] * invN - m1v * m1v;
        a = (a - m0v) * rsqrtf(v0 + 1e-5f) * gamma[tid] + beta[tid];
        b = (b - m1v) * rsqrtf(v1 + 1e-5f) * gamma[HALF + tid] + beta[HALF + tid];
    }

    red0[tid] = a * a;
    red1[tid] = b * b;
    __syncthreads();
    for (int s = 64; s > 0; s >>= 1) {
        if (tid < s) { red0[tid] += red0[tid + s]; red1[tid] += red1[tid + s]; }
        __syncthreads();
    }
    float n0 = fmaxf(sqrtf(red0[0]), 1e-12f);
    float n1 = fmaxf(sqrtf(red1[0]), 1e-12f);
    q0[tid] = a / n0;
    q1[tid] = b / n1;
    __syncthreads();

    const int w = tid >> 5, l = tid & 31;
    for (int j = w; j < NK; j += 4) {
        const float* kr0 = g_k0n + j * HALF;
        const float* kr1 = g_k1n + j * HALF;
        float d0 = kr0[l] * q0[l] + kr0[l + 32] * q0[l + 32]
                 + kr0[l + 64] * q0[l + 64] + kr0[l + 96] * q0[l + 96];
        float d1 = kr1[l] * q1[l] + kr1[l + 32] * q1[l + 32]
                 + kr1[l + 64] * q1[l + 64] + kr1[l + 96] * q1[l + 96];
        #pragma unroll
        for (int off = 16; off; off >>= 1) {
            d0 += __shfl_down_sync(0xffffffffu, d0, off);
            d1 += __shfl_down_sync(0xffffffffu, d1, off);
        }
        if (l == 0) { s0s[j] = d0; s1s[j] = d1; }
    }
    __syncthreads();

    // warp-parallel top-4 per axis (ties -> lowest index, matching lax.top_k)
    if (w < 2) {
        float v = (w == 0) ? s0s[l] : s1s[l];
        #pragma unroll
        for (int p = 0; p < DTK; p++) {
            float bv = v; int bi = l;
            #pragma unroll
            for (int off = 16; off; off >>= 1) {
                float ov = __shfl_down_sync(0xffffffffu, bv, off);
                int oi = __shfl_down_sync(0xffffffffu, bi, off);
                if (ov > bv || (ov == bv && oi < bi)) { bv = ov; bi = oi; }
            }
            bv = __shfl_sync(0xffffffffu, bv, 0);
            bi = __shfl_sync(0xffffffffu, bi, 0);
            if (l == 0) {
                if (w == 0) { ts0[p] = bv; ti0[p] = bi; }
                else        { ts1[p] = bv; ti1[p] = bi; }
            }
            if (l == bi) v = -1e30f;
        }
    }
    __syncthreads();

    if (tid < 16) {
        int i = tid >> 2, j = tid & 3;
        combS[tid] = ts0[i] + ts1[j];
        combI[tid] = ti0[i] * NK + ti1[j];
    }
    __syncthreads();
    if (tid == 0) {
        float m = -1e30f;
        for (int k = 0; k < 16; k++) m = fmaxf(m, combS[k]);
        float s = 0.f;
        for (int k = 0; k < 16; k++) s += expf(combS[k] - m);
        smx = m; ssum = s;
    }
    __syncthreads();
    if (tid < 16) {
        g_idx[(size_t)u * 16 + tid] = (unsigned short)combI[tid];
        g_w[(size_t)u * 16 + tid]   = expf(combS[tid] - smx) / ssum;
    }
}

// ---------------- eh -> C bf16 planes (gelu * softmax weight, scattered) ------
__global__ __launch_bounds__(256)
void transformC_kernel(const float* __restrict__ eh,
                       __nv_bfloat16* __restrict__ c0,
                       __nv_bfloat16* __restrict__ c1) {
    __shared__ float acc[E];
    const int t = blockIdx.x;
    const int tid = threadIdx.x;
    for (int i = tid; i < E; i += 256) acc[i] = 0.f;
    __syncthreads();
    if (tid < NEXP) {
        const int idx = (int)g_idx[(size_t)t * NEXP + tid];
        const float v = eh[(size_t)t * E + idx];
        const float g = 0.5f * v * (1.0f + erff(v * 0.70710678118654752f));
        atomicAdd(&acc[idx], g * g_w[(size_t)t * NEXP + tid]);
    }
    __syncthreads();
    for (int i = tid; i < E; i += 256) {
        const float v = acc[i];
        const __nv_bfloat16 h = __float2bfloat16(v);
        c0[(size_t)t * E + i] = h;
        c1[(size_t)t * E + i] = __float2bfloat16(v - __bfloat162float(h));
    }
}

// ---------------- launch -------------------------------------------------------
extern "C" void kernel_launch(void* const* d_in, const int* in_sizes, int n_in,
                              void* d_out, int out_size) {
    const float* hidden = (const float*)d_in[0];   // [2,512,1024]
    const float* Wq     = (const float*)d_in[1];   // [1024,2048]
    const float* bq     = (const float*)d_in[2];   // [2048]
    const float* gamma  = (const float*)d_in[3];   // [256]
    const float* beta   = (const float*)d_in[4];   // [256]
    const float* k0     = (const float*)d_in[5];   // [32,128]
    const float* k1     = (const float*)d_in[6];   // [32,128]
    const float* down   = (const float*)d_in[7];   // [1024,1024]
    const float* up     = (const float*)d_in[8];   // [1024,1024]
    float* out = (float*)d_out;                    // [2,512,1024]

    float* qbuf = nullptr;
    __nv_bfloat16 *hid = nullptr, *wqT = nullptr, *dwn = nullptr, *upT = nullptr;
    cudaGetSymbolAddress((void**)&qbuf, g_q);
    cudaGetSymbolAddress((void**)&hid, g_hid);
    cudaGetSymbolAddress((void**)&wqT, g_wqT);
    cudaGetSymbolAddress((void**)&dwn, g_dwn);
    cudaGetSymbolAddress((void**)&upT, g_upT);
    float* ehBuf = qbuf;                                   // low 4MB of g_q
    __nv_bfloat16* cp0 = (__nv_bfloat16*)(qbuf + TOK * E); // high 4MB of g_q
    __nv_bfloat16* cp1 = cp0 + TOK * E;

    // all plane conversions in one kernel; key norm + stat zeroing in one
    conv_all<<<11264, 256>>>(hidden, Wq, down, up, hid, wqT, dwn, upT);
    norm_keys_zero_kernel<<<2 * NK + 1, 128>>>(k0, k1);

    // q = hidden @ Wq + bq (6-pass h/m/l: fp32-grade routing)
    gemm_planes<3, 6, 16><<<dim3(HQ / 64, TOK / 128), 256>>>(
        hid, wqT, bq, qbuf, HQ, TOK * D, HQ * D);

    // BN partial sums (mean/var finalized inside score_kernel)
    stats_partial_kernel<<<128, 256>>>();
    score_kernel<<<TOK * HEADS, 128>>>(gamma, beta);

    // eh_all = hidden @ down^T (3-pass h/l); overwrites dead q (low half)
    gemm_planes<2, 3, 32><<<dim3(E / 64, TOK / 128), 256>>>(
        hid, dwn, nullptr, ehBuf, E, TOK * D, E * D);

    // eh -> C planes (gelu * softmax weight, scattered)
    transformC_kernel<<<TOK, 256>>>(ehBuf, cp0, cp1);

    // out = C @ up (3-pass h/l)
    gemm_planes<2, 3, 32><<<dim3(O / 64, TOK / 128), 256>>>(
        cp0, upT, nullptr, out, O, TOK * E, O * E);
}

// round 14
// speedup vs baseline: 1.6513x; 1.3487x over previous
#include <cuda_runtime.h>
#include <cuda_fp16.h>
#include <math.h>
#include <stdint.h>

// ---------------- problem constants -----------------------------------------
#define TOK   1024
#define D     1024
#define HQ    2048
#define HEADS 8
#define QD    256
#define HALF  128
#define NK    32
#define DTK   4
#define NEXP  128
#define E     1024
#define O     1024
#define KDIM  1024
#define WSCALE   64.0f        // weight operand pre-scale (keeps fp16 l-planes normal)
#define IWSCALE  (1.0f / 64.0f)

// ---------------- scratch (~29 MB of __device__ globals) ----------------------
__device__ __align__(256) float g_q[TOK * HQ];          // 8MB; low 4MB->eh, high 4MB->C planes
__device__ __align__(256) __half g_hid[2 * TOK * D];    // 4MB  (h,l planes, unscaled)
__device__ __align__(256) __half g_wqT[2 * HQ * D];     // 8MB  (transposed, x64)
__device__ __align__(256) __half g_dwn[2 * E * D];      // 4MB  (x64)
__device__ __align__(256) __half g_upT[2 * O * E];      // 4MB  (transposed, x64)
__device__ float g_sums[QD];
__device__ float g_sqs[QD];
__device__ float g_k0n[NK * HALF];
__device__ float g_k1n[NK * HALF];
__device__ unsigned short g_idx[TOK * NEXP];
__device__ float g_w[TOK * NEXP];

// ---------------- helpers ----------------------------------------------------
__device__ __forceinline__ uint32_t s2u(const void* p) {
    uint32_t r;
    asm("{ .reg .u64 t; cvta.to.shared.u64 t, %1; cvt.u32.u64 %0, t; }"
        : "=r"(r) : "l"(p));
    return r;
}

// ---------------- fp16 2-plane split warp-MMA GEMM ----------------------------
// C[m0:+128, n0:+64] = oscale * sum_{hh,hl,lh} A_pa @ B_pb^T  (+bias).
// A planes [2][M][K] fp16, B planes [2][N][K] fp16 (pre-transposed, x WSCALE).
// 3 fp16 passes carry ~22 mantissa bits (~fp32). Proven config: static smem
// 48KB, depth-2 cp.async, 8 warps (4Mx2N of 32x32), 2 CTAs/SM.
#define P    2
#define NPAS 3
#define BK   32
__global__ __launch_bounds__(256, 2)
void gemm_planes(const __half* __restrict__ A,
                 const __half* __restrict__ B,
                 const float* __restrict__ bias,
                 float* __restrict__ Cout, int ldc, int aPl, int bPl,
                 float oscale)
{
    constexpr int CPR   = BK / 8;            // 4 16B chunks per row per plane
    constexpr int BKB   = BK * 2;            // 64 bytes per row per plane
    constexpr int APL   = 128 * BKB;         // 8KB
    constexpr int BPL   = 64 * BKB;          // 4KB
    constexpr int STAGE = P * (APL + BPL);   // 24KB
    constexpr int NCHA  = P * 128 * CPR;
    constexpr int NCH   = NCHA + P * 64 * CPR;
    constexpr int NIT   = KDIM / BK;         // 32
    constexpr int KT    = BK / 16;           // 2

    __shared__ __align__(1024) char smem[2 * STAGE];   // 48KB static
    const uint32_t sbase = s2u(smem);
    const int tid = threadIdx.x, w = tid >> 5, l = tid & 31;
    const int m0 = blockIdx.y * 128, n0 = blockIdx.x * 64;
    const int wm = (w >> 1) * 32, wn = (w & 1) * 32;

    float acc[2][4][4];
    #pragma unroll
    for (int a = 0; a < 2; a++)
        #pragma unroll
        for (int b = 0; b < 4; b++)
            #pragma unroll
            for (int c = 0; c < 4; c++) acc[a][b][c] = 0.f;

    auto swz = [](int c, int r) -> int { return c ^ ((r >> 1) & 3); };

    auto issue = [&](int it) {
        const int s = it & 1;
        const int k0 = it * BK;
        const uint32_t sb0 = sbase + (uint32_t)s * STAGE;
        #pragma unroll 2
        for (int id = tid; id < NCH; id += 256) {
            uint32_t dst; const __half* src;
            if (id < NCHA) {
                const int p = id / (128 * CPR);
                const int rem = id - p * 128 * CPR;
                const int r = rem / CPR, c = rem - r * CPR;
                dst = sb0 + (uint32_t)(p * APL + r * BKB + swz(c, r) * 16);
                src = A + (size_t)p * aPl + (size_t)(m0 + r) * KDIM + k0 + c * 8;
            } else {
                const int id2 = id - NCHA;
                const int p = id2 / (64 * CPR);
                const int rem = id2 - p * 64 * CPR;
                const int r = rem / CPR, c = rem - r * CPR;
                dst = sb0 + (uint32_t)(P * APL + p * BPL + r * BKB + swz(c, r) * 16);
                src = B + (size_t)p * bPl + (size_t)(n0 + r) * KDIM + k0 + c * 8;
            }
            asm volatile("cp.async.cg.shared.global [%0], [%1], 16;\n"
                         :: "r"(dst), "l"(src));
        }
        asm volatile("cp.async.commit_group;\n" ::: "memory");
    };

    const int rg = ((l >> 3) & 1) * 8 + (l & 7);
    const int ch = l >> 4;

    issue(0);
    issue(1);
    for (int i = 0; i < NIT; i++) {
        asm volatile("cp.async.wait_group 1;\n" ::: "memory");
        __syncthreads();
        const uint32_t sb0 = sbase + (uint32_t)(i & 1) * STAGE;

        #pragma unroll
        for (int ps = 0; ps < NPAS; ps++) {
            const int PA3[3] = {0, 0, 1}, PB3[3] = {0, 1, 0};
            const int pa = PA3[ps], pb = PB3[ps];
            #pragma unroll
            for (int kt = 0; kt < KT; kt++) {
                uint32_t af[2][4];
                #pragma unroll
                for (int mt = 0; mt < 2; mt++) {
                    const int row = wm + mt * 16 + rg;
                    const int c = kt * 2 + ch;
                    const uint32_t ad = sb0 + (uint32_t)(pa * APL + row * BKB + swz(c, row) * 16);
                    asm volatile("ldmatrix.sync.aligned.m8n8.x4.shared.b16 {%0,%1,%2,%3}, [%4];\n"
                        : "=r"(af[mt][0]), "=r"(af[mt][1]), "=r"(af[mt][2]), "=r"(af[mt][3])
                        : "r"(ad));
                }
                uint32_t bfr[4][2];
                #pragma unroll
                for (int np = 0; np < 2; np++) {
                    const int row = wn + np * 16 + rg;
                    const int c = kt * 2 + ch;
                    const uint32_t ad = sb0 + (uint32_t)(P * APL + pb * BPL + row * BKB + swz(c, row) * 16);
                    uint32_t b0, b1, b2, b3;
                    asm volatile("ldmatrix.sync.aligned.m8n8.x4.shared.b16 {%0,%1,%2,%3}, [%4];\n"
                        : "=r"(b0), "=r"(b1), "=r"(b2), "=r"(b3) : "r"(ad));
                    bfr[np * 2 + 0][0] = b0; bfr[np * 2 + 0][1] = b2;
                    bfr[np * 2 + 1][0] = b1; bfr[np * 2 + 1][1] = b3;
                }
                #pragma unroll
                for (int mt = 0; mt < 2; mt++)
                    #pragma unroll
                    for (int nt = 0; nt < 4; nt++)
                        asm volatile(
                            "mma.sync.aligned.m16n8k16.row.col.f32.f16.f16.f32 "
                            "{%0,%1,%2,%3}, {%4,%5,%6,%7}, {%8,%9}, {%0,%1,%2,%3};\n"
                            : "+f"(acc[mt][nt][0]), "+f"(acc[mt][nt][1]),
                              "+f"(acc[mt][nt][2]), "+f"(acc[mt][nt][3])
                            : "r"(af[mt][0]), "r"(af[mt][1]), "r"(af[mt][2]), "r"(af[mt][3]),
                              "r"(bfr[nt][0]), "r"(bfr[nt][1]));
            }
        }
        __syncthreads();
        if (i + 2 < NIT) issue(i + 2);
        else asm volatile("cp.async.commit_group;\n" ::: "memory");
    }

    #pragma unroll
    for (int mt = 0; mt < 2; mt++) {
        const int row = m0 + wm + mt * 16 + (l >> 2);
        #pragma unroll
        for (int nt = 0; nt < 4; nt++) {
            const int col = n0 + wn + nt * 8 + (l & 3) * 2;
            float b0 = 0.f, b1 = 0.f;
            if (bias) { b0 = bias[col]; b1 = bias[col + 1]; }
            *(float2*)(Cout + (size_t)row * ldc + col) =
                make_float2(acc[mt][nt][0] * oscale + b0, acc[mt][nt][1] * oscale + b1);
            *(float2*)(Cout + (size_t)(row + 8) * ldc + col) =
                make_float2(acc[mt][nt][2] * oscale + b0, acc[mt][nt][3] * oscale + b1);
        }
    }
}

// ---------------- one fused conversion kernel ---------------------------------
// grid: [0,4096) hidden (unscaled) | [4096,8192) down (x64)
//       [8192,10240) Wq^T (x64)    | [10240,11264) up^T (x64)
__global__ __launch_bounds__(256)
void conv_all(const float* __restrict__ hidden, const float* __restrict__ Wq,
              const float* __restrict__ down, const float* __restrict__ up,
              __half* __restrict__ hid, __half* __restrict__ wqT,
              __half* __restrict__ dwn, __half* __restrict__ upT)
{
    const int b = blockIdx.x;
    const int tid = threadIdx.x;
    if (b < 8192) {
        const bool isH = (b < 4096);
        const int i = (isH ? b : b - 4096) * 256 + tid;
        const float v = isH ? hidden[i] : down[i] * WSCALE;
        const __half h = __float2half(v);
        const __half lo = __float2half(v - __half2float(h));
        if (isH) { hid[i] = h; hid[TOK * D + i] = lo; }
        else     { dwn[i] = h; dwn[E * D + i] = lo; }
    } else {
        __shared__ float t[32][33];
        const bool isW = (b < 10240);
        const int idx = isW ? (b - 8192) : (b - 10240);
        const int N = isW ? HQ : O;
        const int nb = N / 32;
        const int nx = (idx % nb) * 32, ky = (idx / nb) * 32;
        const int tx = tid & 31, ty = tid >> 5;   // 32 x 8
        const float* in = isW ? Wq : up;
        #pragma unroll
        for (int j = 0; j < 32; j += 8)
            t[ty + j][tx] = in[(size_t)(ky + ty + j) * N + nx + tx];
        __syncthreads();
        #pragma unroll
        for (int j = 0; j < 32; j += 8) {
            const int n = nx + ty + j;
            const int k = ky + tx;
            const float v = t[tx][ty + j] * WSCALE;
            const __half h = __float2half(v);
            const __half lo = __float2half(v - __half2float(h));
            if (isW) {
                wqT[(size_t)n * KDIM + k] = h;
                wqT[HQ * D + (size_t)n * KDIM + k] = lo;
            } else {
                upT[(size_t)n * KDIM + k] = h;
                upT[O * E + (size_t)n * KDIM + k] = lo;
            }
        }
    }
}

// ---------------- norm keys + zero stats (one launch) --------------------------
__global__ __launch_bounds__(128)
void norm_keys_zero_kernel(const float* __restrict__ k0,
                           const float* __restrict__ k1) {
    const int row = blockIdx.x;
    const int tid = threadIdx.x;
    if (row == 2 * NK) {
        g_sums[tid] = 0.f; g_sums[tid + 128] = 0.f;
        g_sqs[tid] = 0.f;  g_sqs[tid + 128] = 0.f;
        return;
    }
    const float* src = (row < NK) ? (k0 + (size_t)row * HALF)
                                  : (k1 + (size_t)(row - NK) * HALF);
    float* dst = (row < NK) ? (g_k0n + (size_t)row * HALF)
                            : (g_k1n + (size_t)(row - NK) * HALF);
    __shared__ float red[128];
    float v = src[tid];
    red[tid] = v * v;
    __syncthreads();
    for (int s = 64; s > 0; s >>= 1) {
        if (tid < s) red[tid] += red[tid + s];
        __syncthreads();
    }
    float n = sqrtf(red[0]);
    dst[tid] = v / fmaxf(n, 1e-12f);
}

// ---------------- BN partial sums: 128 blocks x 8 rows -------------------------
__global__ __launch_bounds__(256)
void stats_partial_kernel() {
    const int tid = threadIdx.x;
    const int rowStart = blockIdx.x * 8;
    float s = 0.f, sq = 0.f;
    #pragma unroll
    for (int r = 0; r < 8; r++) {
        const float* row = g_q + (size_t)(rowStart + r) * HQ;
        #pragma unroll
        for (int h = 0; h < HEADS; h++) {
            float v = row[h * QD + tid];
            s += v; sq += v * v;
        }
    }
    atomicAdd(&g_sums[tid], s);
    atomicAdd(&g_sqs[tid], sq);
}

// ---------------- score: BN(from raw sums) + L2norm + dots + top4x4 + softmax --
__global__ __launch_bounds__(128)
void score_kernel(const float* __restrict__ gamma,
                  const float* __restrict__ beta) {
    const int u = blockIdx.x;
    const int t = u >> 3;
    const int h = u & 7;
    const int tid = threadIdx.x;

    __shared__ float q0[HALF], q1[HALF];
    __shared__ float red0[128], red1[128];
    __shared__ float s0s[NK], s1s[NK];
    __shared__ float ts0[DTK], ts1[DTK];
    __shared__ int   ti0[DTK], ti1[DTK];
    __shared__ float combS[16];
    __shared__ int   combI[16];
    __shared__ float smx, ssum;

    const float invN = 1.0f / (float)(TOK * HEADS);
    const float* qrow = g_q + (size_t)t * HQ + h * QD;
    float a = qrow[tid];
    float b = qrow[HALF + tid];
    {
        const float m0v = g_sums[tid] * invN;
        const float v0 = g_sqs[tid] * invN - m0v * m0v;
        const float m1v = g_sums[HALF + tid] * invN;
        const float v1 = g_sqs[HALF + tid] * invN - m1v * m1v;
        a = (a - m0v) * rsqrtf(v0 + 1e-5f) * gamma[tid] + beta[tid];
        b = (b - m1v) * rsqrtf(v1 + 1e-5f) * gamma[HALF + tid] + beta[HALF + tid];
    }

    red0[tid] = a * a;
    red1[tid] = b * b;
    __syncthreads();
    for (int s = 64; s > 0; s >>= 1) {
        if (tid < s) { red0[tid] += red0[tid + s]; red1[tid] += red1[tid + s]; }
        __syncthreads();
    }
    float n0 = fmaxf(sqrtf(red0[0]), 1e-12f);
    float n1 = fmaxf(sqrtf(red1[0]), 1e-12f);
    q0[tid] = a / n0;
    q1[tid] = b / n1;
    __syncthreads();

    const int w = tid >> 5, l = tid & 31;
    for (int j = w; j < NK; j += 4) {
        const float* kr0 = g_k0n + j * HALF;
        const float* kr1 = g_k1n + j * HALF;
        float d0 = kr0[l] * q0[l] + kr0[l + 32] * q0[l + 32]
                 + kr0[l + 64] * q0[l + 64] + kr0[l + 96] * q0[l + 96];
        float d1 = kr1[l] * q1[l] + kr1[l + 32] * q1[l + 32]
                 + kr1[l + 64] * q1[l + 64] + kr1[l + 96] * q1[l + 96];
        #pragma unroll
        for (int off = 16; off; off >>= 1) {
            d0 += __shfl_down_sync(0xffffffffu, d0, off);
            d1 += __shfl_down_sync(0xffffffffu, d1, off);
        }
        if (l == 0) { s0s[j] = d0; s1s[j] = d1; }
    }
    __syncthreads();

    // warp-parallel top-4 per axis (ties -> lowest index, matching lax.top_k)
    if (w < 2) {
        float v = (w == 0) ? s0s[l] : s1s[l];
        #pragma unroll
        for (int p = 0; p < DTK; p++) {
            float bv = v; int bi = l;
            #pragma unroll
            for (int off = 16; off; off >>= 1) {
                float ov = __shfl_down_sync(0xffffffffu, bv, off);
                int oi = __shfl_down_sync(0xffffffffu, bi, off);
                if (ov > bv || (ov == bv && oi < bi)) { bv = ov; bi = oi; }
            }
            bv = __shfl_sync(0xffffffffu, bv, 0);
            bi = __shfl_sync(0xffffffffu, bi, 0);
            if (l == 0) {
                if (w == 0) { ts0[p] = bv; ti0[p] = bi; }
                else        { ts1[p] = bv; ti1[p] = bi; }
            }
            if (l == bi) v = -1e30f;
        }
    }
    __syncthreads();

    if (tid < 16) {
        int i = tid >> 2, j = tid & 3;
        combS[tid] = ts0[i] + ts1[j];
        combI[tid] = ti0[i] * NK + ti1[j];
    }
    __syncthreads();
    if (tid == 0) {
        float m = -1e30f;
        for (int k = 0; k < 16; k++) m = fmaxf(m, combS[k]);
        float s = 0.f;
        for (int k = 0; k < 16; k++) s += expf(combS[k] - m);
        smx = m; ssum = s;
    }
    __syncthreads();
    if (tid < 16) {
        g_idx[(size_t)u * 16 + tid] = (unsigned short)combI[tid];
        g_w[(size_t)u * 16 + tid]   = expf(combS[tid] - smx) / ssum;
    }
}

// ---------------- eh -> C fp16 planes (gelu * softmax weight, scattered) ------
__global__ __launch_bounds__(256)
void transformC_kernel(const float* __restrict__ eh,
                       __half* __restrict__ c0,
                       __half* __restrict__ c1) {
    __shared__ float acc[E];
    const int t = blockIdx.x;
    const int tid = threadIdx.x;
    for (int i = tid; i < E; i += 256) acc[i] = 0.f;
    __syncthreads();
    if (tid < NEXP) {
        const int idx = (int)g_idx[(size_t)t * NEXP + tid];
        const float v = eh[(size_t)t * E + idx];
        const float g = 0.5f * v * (1.0f + erff(v * 0.70710678118654752f));
        atomicAdd(&acc[idx], g * g_w[(size_t)t * NEXP + tid]);
    }
    __syncthreads();
    for (int i = tid; i < E; i += 256) {
        const float v = acc[i];
        const __half h = __float2half(v);
        c0[(size_t)t * E + i] = h;
        c1[(size_t)t * E + i] = __float2half(v - __half2float(h));
    }
}

// ---------------- launch -------------------------------------------------------
extern "C" void kernel_launch(void* const* d_in, const int* in_sizes, int n_in,
                              void* d_out, int out_size) {
    const float* hidden = (const float*)d_in[0];   // [2,512,1024]
    const float* Wq     = (const float*)d_in[1];   // [1024,2048]
    const float* bq     = (const float*)d_in[2];   // [2048]
    const float* gamma  = (const float*)d_in[3];   // [256]
    const float* beta   = (const float*)d_in[4];   // [256]
    const float* k0     = (const float*)d_in[5];   // [32,128]
    const float* k1     = (const float*)d_in[6];   // [32,128]
    const float* down   = (const float*)d_in[7];   // [1024,1024]
    const float* up     = (const float*)d_in[8];   // [1024,1024]
    float* out = (float*)d_out;                    // [2,512,1024]

    float* qbuf = nullptr;
    __half *hid = nullptr, *wqT = nullptr, *dwn = nullptr, *upT = nullptr;
    cudaGetSymbolAddress((void**)&qbuf, g_q);
    cudaGetSymbolAddress((void**)&hid, g_hid);
    cudaGetSymbolAddress((void**)&wqT, g_wqT);
    cudaGetSymbolAddress((void**)&dwn, g_dwn);
    cudaGetSymbolAddress((void**)&upT, g_upT);
    float* ehBuf = qbuf;                             // low 4MB of g_q
    __half* cp0 = (__half*)(qbuf + TOK * E);         // high 4MB of g_q
    __half* cp1 = cp0 + TOK * E;

    conv_all<<<11264, 256>>>(hidden, Wq, down, up, hid, wqT, dwn, upT);
    norm_keys_zero_kernel<<<2 * NK + 1, 128>>>(k0, k1);

    // q = hidden @ Wq + bq  (3-pass fp16 split, ~fp32 accuracy for routing)
    gemm_planes<<<dim3(HQ / 64, TOK / 128), 256>>>(
        hid, wqT, bq, qbuf, HQ, TOK * D, HQ * D, IWSCALE);

    stats_partial_kernel<<<128, 256>>>();
    score_kernel<<<TOK * HEADS, 128>>>(gamma, beta);

    // eh_all = hidden @ down^T
    gemm_planes<<<dim3(E / 64, TOK / 128), 256>>>(
        hid, dwn, nullptr, ehBuf, E, TOK * D, E * D, IWSCALE);

    // eh -> C fp16 planes (gelu * softmax weight, scattered)
    transformC_kernel<<<TOK, 256>>>(ehBuf, cp0, cp1);

    // out = C @ up
    gemm_planes<<<dim3(O / 64, TOK / 128), 256>>>(
        cp0, upT, nullptr, out, O, TOK * E, O * E, IWSCALE);
}